// round 11
// baseline (speedup 1.0000x reference)
#include <cuda_runtime.h>
#include <cuda_bf16.h>
#include <cstdint>

// Gather: out[g][row][j*32+k] = in[row][g*512 + j*64 + k]
//   out flat float4 idx i: g=i>>20, row=(i>>6)&16383, v=i&63
//   src (float4 units) = row*1024 + g*128 + (v>>3)*16 + (v&7)
//
// R10 (44.13us: front-batched MLP=4, const stride, regs=30, occ 84.5%)
// extended along the proven axis: front-batched MLP=8 per thread, same
// grid-strided linear mapping and constant stride. 8x16B payload = 32 regs
// + addressing ~= 44 regs -> occupancy still capped by the 32-warp limit,
// not registers. Expect the lat/MLP term to shrink further; bandwidth
// ceiling (~5.9 TB/s on 256 MiB/replay) bounds the gain.

#define GRID_BLOCKS 4096u
#define STRIDE      (GRID_BLOCKS * 256u)   // 2^20 float4s per sweep

__global__ void __launch_bounds__(256)
fuse_slice_cat_kernel(const float4* __restrict__ in, float4* __restrict__ out)
{
    const unsigned int i0 = blockIdx.x * 256u + threadIdx.x;

    unsigned int srcI[8];
    #pragma unroll
    for (int it = 0; it < 8; ++it) {
        unsigned int i   = i0 + (unsigned)it * STRIDE;
        unsigned int g   = i >> 20;
        unsigned int row = (i >> 6) & 16383u;
        unsigned int v   = i & 63u;
        srcI[it] = row * 1024u + g * 128u + (v >> 3) * 16u + (v & 7u);
    }

    float4 r[8];
    #pragma unroll
    for (int it = 0; it < 8; ++it)      // 8 loads in flight before any store
        r[it] = in[srcI[it]];

    #pragma unroll
    for (int it = 0; it < 8; ++it)
        out[i0 + (unsigned)it * STRIDE] = r[it];
}

extern "C" void kernel_launch(void* const* d_in, const int* in_sizes, int n_in,
                              void* d_out, int out_size)
{
    const float4* in  = (const float4*)d_in[0];
    float4*       out = (float4*)d_out;

    // 2^23 float4s total; 8 per thread -> 2^20 threads -> 4096 blocks of 256.
    fuse_slice_cat_kernel<<<GRID_BLOCKS, 256>>>(in, out);
}